// round 2
// baseline (speedup 1.0000x reference)
#include <cuda_runtime.h>
#include <math.h>
#include <float.h>

#define BB   8
#define NN   2048
#define BN   16384
#define KNB  16
#define DP   64
#define DM   128

// ---------------- scratch (static device globals; no allocation) ----------------
__device__ int   g_knn[BN * KNB];
__device__ float g_q[BN * DM];
__device__ float g_k[BN * DM];
__device__ float g_v[BN * DM];
__device__ float g_res[BN * DM];

// =================================================================================
// K1: KNN — warp per query. Each lane holds 64 candidate distances in registers.
// Select 32 smallest in sorted (value, index) lexicographic order (== stable
// argsort), emit every other one (positions 0,2,...,30) as the 16 neighbors.
// =================================================================================
__global__ __launch_bounds__(256) void knn_kernel(const float* __restrict__ xyz)
{
    int warp = threadIdx.x >> 5;
    int lane = threadIdx.x & 31;
    int qi   = blockIdx.x * 8 + warp;       // global (b*N + n)
    int nbase = qi & ~(NN - 1);
    const float* Xb = xyz + (size_t)nbase * 3;
    int ql = qi & (NN - 1);

    float qx = Xb[ql*3+0], qy = Xb[ql*3+1], qz = Xb[ql*3+2];
    float sqq = __fadd_rn(__fadd_rn(__fmul_rn(qx,qx), __fmul_rn(qy,qy)), __fmul_rn(qz,qz));

    float dv[64];
#pragma unroll
    for (int j = 0; j < 64; ++j) {
        int c = lane + (j << 5);
        float cx = Xb[c*3+0], cy = Xb[c*3+1], cz = Xb[c*3+2];
        float sqc = __fadd_rn(__fadd_rn(__fmul_rn(cx,cx), __fmul_rn(cy,cy)), __fmul_rn(cz,cz));
        float dot = __fadd_rn(__fadd_rn(__fmul_rn(qx,cx), __fmul_rn(qy,cy)), __fmul_rn(qz,cz));
        dv[j] = __fsub_rn(__fadd_rn(sqq, sqc), __fmul_rn(2.0f, dot));
    }

    float tv = -FLT_MAX; int ti = -1;   // last selected (value, idx)
#pragma unroll 1
    for (int r = 0; r < 32; ++r) {
        float mv = FLT_MAX; int mi = 0x7FFFFFFF;
#pragma unroll
        for (int j = 0; j < 64; ++j) {
            float v = dv[j]; int ci = lane + (j << 5);
            bool valid  = (v > tv) || ((v == tv) && (ci > ti));
            bool better = (v < mv) || ((v == mv) && (ci < mi));
            if (valid && better) { mv = v; mi = ci; }
        }
#pragma unroll
        for (int off = 16; off > 0; off >>= 1) {
            float ov = __shfl_down_sync(0xFFFFFFFFu, mv, off);
            int   oi = __shfl_down_sync(0xFFFFFFFFu, mi, off);
            if ((ov < mv) || ((ov == mv) && (oi < mi))) { mv = ov; mi = oi; }
        }
        mv = __shfl_sync(0xFFFFFFFFu, mv, 0);
        mi = __shfl_sync(0xFFFFFFFFu, mi, 0);
        tv = mv; ti = mi;
        if (((r & 1) == 0) && lane == 0)
            g_knn[qi * KNB + (r >> 1)] = mi;   // local index within batch
    }
}

// =================================================================================
// K2: x = feat@W1 + b1 ; q/k/v = x@{Wq,Wk,Wv}.  64-row tiles, 256 threads.
// =================================================================================
__global__ __launch_bounds__(256) void proj_kernel(
    const float* __restrict__ feat, const float* __restrict__ W1, const float* __restrict__ b1,
    const float* __restrict__ Wq, const float* __restrict__ Wk, const float* __restrict__ Wv)
{
    extern __shared__ float sm[];
    float* sF = sm;          // 64*64   = 4096
    float* sX = sm + 4096;   // 64*128  = 8192
    float* sW = sm + 12288;  // 128*128 = 16384
    int tid = threadIdx.x;
    int row0 = blockIdx.x * 64;

    for (int i = tid; i < 4096; i += 256) sF[i] = feat[(size_t)row0 * DP + i];
    for (int i = tid; i < 8192; i += 256) sW[i] = W1[i];
    __syncthreads();

    int ty = tid >> 5, tx = tid & 31;
    float acc[8][4];
#pragma unroll
    for (int i = 0; i < 8; ++i)
#pragma unroll
        for (int j = 0; j < 4; ++j) acc[i][j] = 0.f;

#pragma unroll 4
    for (int kk = 0; kk < 64; ++kk) {
        float a[8], w[4];
#pragma unroll
        for (int i = 0; i < 8; ++i) a[i] = sF[(ty + 8*i)*64 + kk];
#pragma unroll
        for (int j = 0; j < 4; ++j) w[j] = sW[kk*128 + tx + 32*j];
#pragma unroll
        for (int i = 0; i < 8; ++i)
#pragma unroll
            for (int j = 0; j < 4; ++j) acc[i][j] = fmaf(a[i], w[j], acc[i][j]);
    }
#pragma unroll
    for (int i = 0; i < 8; ++i)
#pragma unroll
        for (int j = 0; j < 4; ++j)
            sX[(ty + 8*i)*128 + tx + 32*j] = acc[i][j] + __ldg(&b1[tx + 32*j]);
    __syncthreads();

    const float* Ws[3] = {Wq, Wk, Wv};
    float* Gs[3];
    Gs[0] = g_q; Gs[1] = g_k; Gs[2] = g_v;

    for (int p = 0; p < 3; ++p) {
        for (int i = tid; i < 16384; i += 256) sW[i] = Ws[p][i];
        __syncthreads();
#pragma unroll
        for (int i = 0; i < 8; ++i)
#pragma unroll
            for (int j = 0; j < 4; ++j) acc[i][j] = 0.f;
#pragma unroll 4
        for (int kk = 0; kk < 128; ++kk) {
            float a[8], w[4];
#pragma unroll
            for (int i = 0; i < 8; ++i) a[i] = sX[(ty + 8*i)*128 + kk];
#pragma unroll
            for (int j = 0; j < 4; ++j) w[j] = sW[kk*128 + tx + 32*j];
#pragma unroll
            for (int i = 0; i < 8; ++i)
#pragma unroll
                for (int j = 0; j < 4; ++j) acc[i][j] = fmaf(a[i], w[j], acc[i][j]);
        }
        float* G = Gs[p];
#pragma unroll
        for (int i = 0; i < 8; ++i)
#pragma unroll
            for (int j = 0; j < 4; ++j)
                G[(size_t)(row0 + ty + 8*i)*DM + tx + 32*j] = acc[i][j];
        __syncthreads();
    }
}

// 128x128x128 fp32 GEMM fragment: thread (ty 0..15, tx 0..15), 8x8 register tile.
// sA pitch 129 (conflict-free dual-broadcast a-loads).
__device__ __forceinline__ void gemm128(const float* __restrict__ sA,
                                        const float* __restrict__ sW,
                                        int ty, int tx, float acc[8][8])
{
#pragma unroll 4
    for (int kk = 0; kk < 128; ++kk) {
        float a[8], w[8];
#pragma unroll
        for (int i = 0; i < 8; ++i) a[i] = sA[(ty + 16*i)*129 + kk];
#pragma unroll
        for (int j = 0; j < 8; ++j) w[j] = sW[kk*128 + tx + 16*j];
#pragma unroll
        for (int i = 0; i < 8; ++i)
#pragma unroll
            for (int j = 0; j < 8; ++j) acc[i][j] = fmaf(a[i], w[j], acc[i][j]);
    }
}

// =================================================================================
// K3: fused attention core. 8 queries/block -> 128 (query,neighbor) rows.
// =================================================================================
__global__ __launch_bounds__(256, 1) void attn_kernel(
    const float* __restrict__ xyz,
    const float* __restrict__ Wd1, const float* __restrict__ bd1,
    const float* __restrict__ Wd2, const float* __restrict__ bd2,
    const float* __restrict__ Wg1, const float* __restrict__ bg1,
    const float* __restrict__ Wg2, const float* __restrict__ bg2,
    float* __restrict__ out_attn, int write_attn)
{
    extern __shared__ float sm[];
    float* sA = sm;                 // 128*129 = 16512
    float* sP = sm + 16512;         // 128*129 = 16512
    float* sW = sm + 33024;         // 128*128 = 16384
    float* sQ = sm + 49408;         // 8*128   = 1024
    float* sD = sm + 50432;         // 128*3   = 384
    int*   sI = (int*)(sm + 50816); // 128

    int tid = threadIdx.x;
    int q0 = blockIdx.x * 8;               // global row of first query
    int nbase = q0 & ~(NN - 1);

    if (tid < 128) {
        int r  = tid;
        int qg = q0 + (r >> 4);
        int idx = g_knn[qg * KNB + (r & 15)];
        sI[r] = idx;
        int cg = nbase + idx;
        sD[r*3+0] = xyz[qg*3+0] - xyz[cg*3+0];
        sD[r*3+1] = xyz[qg*3+1] - xyz[cg*3+1];
        sD[r*3+2] = xyz[qg*3+2] - xyz[cg*3+2];
    }
    for (int i = tid; i < 1024; i += 256) sQ[i] = g_q[(size_t)q0 * DM + i];
    for (int i = tid; i < 384; i += 256) sW[i] = Wd1[i];   // FIX: full 384 loads
    __syncthreads();

    // T1 -> sA
    for (int e = tid; e < 16384; e += 256) {
        int r = e >> 7, c = e & 127;
        float t = __fmul_rn(sD[r*3+0], sW[c]);
        t = fmaf(sD[r*3+1], sW[128 + c], t);
        t = fmaf(sD[r*3+2], sW[256 + c], t);
        t += __ldg(&bd1[c]);
        sA[r*129 + c] = fmaxf(t, 0.0f);
    }
    __syncthreads();
    for (int i = tid; i < 4096; i += 256) ((float4*)sW)[i] = ((const float4*)Wd2)[i];
    __syncthreads();

    int ty = tid >> 4, tx = tid & 15;
    float acc[8][8];
#pragma unroll
    for (int i = 0; i < 8; ++i)
#pragma unroll
        for (int j = 0; j < 8; ++j) acc[i][j] = 0.f;
    gemm128(sA, sW, ty, tx, acc);
    {
        float bb[8];
#pragma unroll
        for (int j = 0; j < 8; ++j) bb[j] = __ldg(&bd2[tx + 16*j]);
#pragma unroll
        for (int i = 0; i < 8; ++i)
#pragma unroll
            for (int j = 0; j < 8; ++j)
                sP[(ty + 16*i)*129 + tx + 16*j] = acc[i][j] + bb[j];
    }
    __syncthreads();

    // H -> sA (overwrite T1); prefetch Wg1
    for (int e = tid; e < 16384; e += 256) {
        int r = e >> 7, c = e & 127;
        float kv = g_k[(size_t)(nbase + sI[r]) * DM + c];
        sA[r*129 + c] = (sQ[(r >> 4)*128 + c] - kv) + sP[r*129 + c];
    }
    for (int i = tid; i < 4096; i += 256) ((float4*)sW)[i] = ((const float4*)Wg1)[i];
    __syncthreads();

#pragma unroll
    for (int i = 0; i < 8; ++i)
#pragma unroll
        for (int j = 0; j < 8; ++j) acc[i][j] = 0.f;
    gemm128(sA, sW, ty, tx, acc);
    __syncthreads();   // all reads of sA(H) complete
    {
        float bb[8];
#pragma unroll
        for (int j = 0; j < 8; ++j) bb[j] = __ldg(&bg1[tx + 16*j]);
#pragma unroll
        for (int i = 0; i < 8; ++i)
#pragma unroll
            for (int j = 0; j < 8; ++j)
                sA[(ty + 16*i)*129 + tx + 16*j] = fmaxf(acc[i][j] + bb[j], 0.0f);
    }
    for (int i = tid; i < 4096; i += 256) ((float4*)sW)[i] = ((const float4*)Wg2)[i];
    __syncthreads();

#pragma unroll
    for (int i = 0; i < 8; ++i)
#pragma unroll
        for (int j = 0; j < 8; ++j) acc[i][j] = 0.f;
    gemm128(sA, sW, ty, tx, acc);
    __syncthreads();
    {
        const float SC = 0.08838834764831845f;  // 1/sqrt(128)
        float bb[8];
#pragma unroll
        for (int j = 0; j < 8; ++j) bb[j] = __ldg(&bg2[tx + 16*j]);
#pragma unroll
        for (int i = 0; i < 8; ++i)
#pragma unroll
            for (int j = 0; j < 8; ++j)
                sA[(ty + 16*i)*129 + tx + 16*j] = (acc[i][j] + bb[j]) * SC;
    }
    __syncthreads();

    // softmax over neighbor axis per channel; emit attn + accumulate res
    for (int item = tid; item < 1024; item += 256) {
        int q = item >> 7, c = item & 127;
        int rb = q << 4;
        float m = -FLT_MAX;
#pragma unroll
        for (int nb = 0; nb < 16; ++nb) m = fmaxf(m, sA[(rb + nb)*129 + c]);
        float s = 0.f;
#pragma unroll
        for (int nb = 0; nb < 16; ++nb) {
            float e = expf(sA[(rb + nb)*129 + c] - m);
            sA[(rb + nb)*129 + c] = e;
            s += e;
        }
        float inv = 1.0f / s;
        float racc = 0.f;
        size_t obase = ((size_t)(q0 + q) * KNB) * DM + c;
#pragma unroll
        for (int nb = 0; nb < 16; ++nb) {
            int r = rb + nb;
            float a = sA[r*129 + c] * inv;
            if (write_attn) out_attn[obase + (size_t)nb * DM] = a;
            float vv = g_v[(size_t)(nbase + sI[r]) * DM + c];
            racc = fmaf(a, vv + sP[r*129 + c], racc);
        }
        g_res[(size_t)(q0 + q) * DM + c] = racc;
    }
}

// =================================================================================
// K4: out_res = g_res @ W2 + b2 + features  (16384x128 @ 128x64)
// =================================================================================
__global__ __launch_bounds__(256) void final_kernel(
    const float* __restrict__ W2, const float* __restrict__ b2,
    const float* __restrict__ feat, float* __restrict__ out_res)
{
    extern __shared__ float sm[];
    float* sR  = sm;        // 64*128 = 8192
    float* sW2 = sm + 8192; // 128*64 = 8192
    int tid = threadIdx.x;
    int row0 = blockIdx.x * 64;

    for (int i = tid; i < 8192; i += 256) {
        sR[i]  = g_res[(size_t)row0 * DM + i];
        sW2[i] = W2[i];
    }
    __syncthreads();

    int ty = tid >> 5, tx = tid & 31;
    float acc[8][2];
#pragma unroll
    for (int i = 0; i < 8; ++i) { acc[i][0] = 0.f; acc[i][1] = 0.f; }

#pragma unroll 4
    for (int kk = 0; kk < 128; ++kk) {
        float a[8], w[2];
#pragma unroll
        for (int i = 0; i < 8; ++i) a[i] = sR[(ty + 8*i)*128 + kk];
        w[0] = sW2[kk*64 + tx];
        w[1] = sW2[kk*64 + tx + 32];
#pragma unroll
        for (int i = 0; i < 8; ++i) {
            acc[i][0] = fmaf(a[i], w[0], acc[i][0]);
            acc[i][1] = fmaf(a[i], w[1], acc[i][1]);
        }
    }
#pragma unroll
    for (int i = 0; i < 8; ++i)
#pragma unroll
        for (int j = 0; j < 2; ++j) {
            int r = ty + 8*i, c = tx + 32*j;
            out_res[(size_t)(row0 + r)*DP + c] =
                acc[i][j] + __ldg(&b2[c]) + feat[(size_t)(row0 + r)*DP + c];
        }
}

// =================================================================================
// launch
// =================================================================================
extern "C" void kernel_launch(void* const* d_in, const int* in_sizes, int n_in,
                              void* d_out, int out_size)
{
    const float* xyz  = (const float*)d_in[0];
    const float* feat = (const float*)d_in[1];
    const float* W1   = (const float*)d_in[2];
    const float* b1   = (const float*)d_in[3];
    const float* W2   = (const float*)d_in[4];
    const float* b2   = (const float*)d_in[5];
    const float* Wd1  = (const float*)d_in[6];
    const float* bd1  = (const float*)d_in[7];
    const float* Wd2  = (const float*)d_in[8];
    const float* bd2  = (const float*)d_in[9];
    const float* Wg1  = (const float*)d_in[10];
    const float* bg1  = (const float*)d_in[11];
    const float* Wg2  = (const float*)d_in[12];
    const float* bg2  = (const float*)d_in[13];
    const float* Wq   = (const float*)d_in[14];
    const float* Wk   = (const float*)d_in[15];
    const float* Wv   = (const float*)d_in[16];

    float* out = (float*)d_out;
    const long long RES_E = (long long)BN * DP;           // 1,048,576
    const long long ATT_E = (long long)BN * KNB * DM;     // 33,554,432

    float* out_res  = out;
    float* out_attn = out;
    int wr = 1, wa = 1;
    long long osz = (long long)out_size;
    if (osz >= RES_E + ATT_E) {
        out_attn = out + RES_E;                 // tuple (res, attn) concatenated
    } else if (osz == ATT_E) {
        wr = 0;                                 // attn only
    } else {
        wa = 0;                                 // res only
    }

    const size_t PROJ_SMEM = (4096 + 8192 + 16384) * sizeof(float);            // 112 KB
    const size_t ATTN_SMEM = (16512 + 16512 + 16384 + 1024 + 384) * sizeof(float)
                             + 128 * sizeof(int);                               // ~199 KB
    const size_t FIN_SMEM  = 16384 * sizeof(float);                             // 64 KB

    cudaFuncSetAttribute(proj_kernel,  cudaFuncAttributeMaxDynamicSharedMemorySize, (int)PROJ_SMEM);
    cudaFuncSetAttribute(attn_kernel,  cudaFuncAttributeMaxDynamicSharedMemorySize, (int)ATTN_SMEM);
    cudaFuncSetAttribute(final_kernel, cudaFuncAttributeMaxDynamicSharedMemorySize, (int)FIN_SMEM);

    knn_kernel<<<BN / 8, 256>>>(xyz);
    proj_kernel<<<BN / 64, 256, PROJ_SMEM>>>(feat, W1, b1, Wq, Wk, Wv);
    attn_kernel<<<BN / 8, 256, ATTN_SMEM>>>(xyz, Wd1, bd1, Wd2, bd2,
                                            Wg1, bg1, Wg2, bg2, out_attn, wa);
    if (wr)
        final_kernel<<<BN / 64, 256, FIN_SMEM>>>(W2, b2, feat, out_res);
}

// round 5
// speedup vs baseline: 1.5368x; 1.5368x over previous
#include <cuda_runtime.h>
#include <cuda_bf16.h>
#include <mma.h>
#include <cstdint>
#include <math.h>
#include <float.h>

using namespace nvcuda;

#define NN   2048
#define BN   16384
#define KNB  16
#define DP   64
#define DM   128

// ---------------- scratch (static device globals; no allocation) ----------------
__device__ int   g_knn[BN * KNB];
__device__ float g_q[BN * DM];
__device__ float g_k[BN * DM];
__device__ float g_v[BN * DM];
__device__ float g_res[BN * DM];
// bf16 copies of Wd2 / Wg1 / Wg2, plain row-major [k][n] 128x128
__device__ __align__(16) __nv_bfloat16 g_WB[3][16384];

__device__ __forceinline__ uint32_t pack_bf16(float lo, float hi) {
    uint32_t r;
    asm("cvt.rn.bf16x2.f32 %0, %1, %2;" : "=r"(r) : "f"(hi), "f"(lo));
    return r;
}

// =================================================================================
// K0: convert Wd2/Wg1/Wg2 to bf16 row-major
// =================================================================================
__global__ void wprep_kernel(const float* __restrict__ Wd2,
                             const float* __restrict__ Wg1,
                             const float* __restrict__ Wg2)
{
    const float* W = (blockIdx.x == 0) ? Wd2 : (blockIdx.x == 1) ? Wg1 : Wg2;
    __nv_bfloat16* dst = &g_WB[blockIdx.x][0];
    for (int e = threadIdx.x; e < 16384; e += blockDim.x)
        dst[e] = __float2bfloat16(W[e]);
}

// =================================================================================
// K1: KNN (unchanged from passing R2 version)
// =================================================================================
__global__ __launch_bounds__(256) void knn_kernel(const float* __restrict__ xyz)
{
    int warp = threadIdx.x >> 5;
    int lane = threadIdx.x & 31;
    int qi   = blockIdx.x * 8 + warp;
    int nbase = qi & ~(NN - 1);
    const float* Xb = xyz + (size_t)nbase * 3;
    int ql = qi & (NN - 1);

    float qx = Xb[ql*3+0], qy = Xb[ql*3+1], qz = Xb[ql*3+2];
    float sqq = __fadd_rn(__fadd_rn(__fmul_rn(qx,qx), __fmul_rn(qy,qy)), __fmul_rn(qz,qz));

    float dv[64];
#pragma unroll
    for (int j = 0; j < 64; ++j) {
        int c = lane + (j << 5);
        float cx = Xb[c*3+0], cy = Xb[c*3+1], cz = Xb[c*3+2];
        float sqc = __fadd_rn(__fadd_rn(__fmul_rn(cx,cx), __fmul_rn(cy,cy)), __fmul_rn(cz,cz));
        float dot = __fadd_rn(__fadd_rn(__fmul_rn(qx,cx), __fmul_rn(qy,cy)), __fmul_rn(qz,cz));
        dv[j] = __fsub_rn(__fadd_rn(sqq, sqc), __fmul_rn(2.0f, dot));
    }

    float tv = -FLT_MAX; int ti = -1;
#pragma unroll 1
    for (int r = 0; r < 32; ++r) {
        float mv = FLT_MAX; int mi = 0x7FFFFFFF;
#pragma unroll
        for (int j = 0; j < 64; ++j) {
            float v = dv[j]; int ci = lane + (j << 5);
            bool valid  = (v > tv) || ((v == tv) && (ci > ti));
            bool better = (v < mv) || ((v == mv) && (ci < mi));
            if (valid && better) { mv = v; mi = ci; }
        }
#pragma unroll
        for (int off = 16; off > 0; off >>= 1) {
            float ov = __shfl_down_sync(0xFFFFFFFFu, mv, off);
            int   oi = __shfl_down_sync(0xFFFFFFFFu, mi, off);
            if ((ov < mv) || ((ov == mv) && (oi < mi))) { mv = ov; mi = oi; }
        }
        mv = __shfl_sync(0xFFFFFFFFu, mv, 0);
        mi = __shfl_sync(0xFFFFFFFFu, mi, 0);
        tv = mv; ti = mi;
        if (((r & 1) == 0) && lane == 0)
            g_knn[qi * KNB + (r >> 1)] = mi;
    }
}

// =================================================================================
// K2: x = feat@W1 + b1 ; q/k/v = x@{Wq,Wk,Wv}  (unchanged)
// =================================================================================
__global__ __launch_bounds__(256) void proj_kernel(
    const float* __restrict__ feat, const float* __restrict__ W1, const float* __restrict__ b1,
    const float* __restrict__ Wq, const float* __restrict__ Wk, const float* __restrict__ Wv)
{
    extern __shared__ float sm[];
    float* sF = sm;
    float* sX = sm + 4096;
    float* sW = sm + 12288;
    int tid = threadIdx.x;
    int row0 = blockIdx.x * 64;

    for (int i = tid; i < 4096; i += 256) sF[i] = feat[(size_t)row0 * DP + i];
    for (int i = tid; i < 8192; i += 256) sW[i] = W1[i];
    __syncthreads();

    int ty = tid >> 5, tx = tid & 31;
    float acc[8][4];
#pragma unroll
    for (int i = 0; i < 8; ++i)
#pragma unroll
        for (int j = 0; j < 4; ++j) acc[i][j] = 0.f;

#pragma unroll 4
    for (int kk = 0; kk < 64; ++kk) {
        float a[8], w[4];
#pragma unroll
        for (int i = 0; i < 8; ++i) a[i] = sF[(ty + 8*i)*64 + kk];
#pragma unroll
        for (int j = 0; j < 4; ++j) w[j] = sW[kk*128 + tx + 32*j];
#pragma unroll
        for (int i = 0; i < 8; ++i)
#pragma unroll
            for (int j = 0; j < 4; ++j) acc[i][j] = fmaf(a[i], w[j], acc[i][j]);
    }
#pragma unroll
    for (int i = 0; i < 8; ++i)
#pragma unroll
        for (int j = 0; j < 4; ++j)
            sX[(ty + 8*i)*128 + tx + 32*j] = acc[i][j] + __ldg(&b1[tx + 32*j]);
    __syncthreads();

    const float* Ws[3] = {Wq, Wk, Wv};
    float* Gs[3]; Gs[0] = g_q; Gs[1] = g_k; Gs[2] = g_v;

    for (int p = 0; p < 3; ++p) {
        for (int i = tid; i < 16384; i += 256) sW[i] = Ws[p][i];
        __syncthreads();
#pragma unroll
        for (int i = 0; i < 8; ++i)
#pragma unroll
            for (int j = 0; j < 4; ++j) acc[i][j] = 0.f;
#pragma unroll 4
        for (int kk = 0; kk < 128; ++kk) {
            float a[8], w[4];
#pragma unroll
            for (int i = 0; i < 8; ++i) a[i] = sX[(ty + 8*i)*128 + kk];
#pragma unroll
            for (int j = 0; j < 4; ++j) w[j] = sW[kk*128 + tx + 32*j];
#pragma unroll
            for (int i = 0; i < 8; ++i)
#pragma unroll
                for (int j = 0; j < 4; ++j) acc[i][j] = fmaf(a[i], w[j], acc[i][j]);
        }
        float* G = Gs[p];
#pragma unroll
        for (int i = 0; i < 8; ++i)
#pragma unroll
            for (int j = 0; j < 4; ++j)
                G[(size_t)(row0 + ty + 8*i)*DM + tx + 32*j] = acc[i][j];
        __syncthreads();
    }
}

// =================================================================================
// K3: fused attention core via wmma bf16 (HMMA). 8 queries/block -> 128 rows.
// Warp w owns query w (rows 16w..16w+15 = its 16 neighbors): all GEMM A-rows,
// epilogues, and the neighbor-axis softmax are warp-local. Only 2 block syncs.
// =================================================================================
#define PA 136          // bf16 pitch of A/P tiles (272 B rows, 16B-aligned)
// smem byte offsets
#define SO_SI   0       // int[128]
#define SO_SD   512     // float[384]
#define SO_WD1  2048    // float[384]
#define SO_BD1  3584    // float[128]
#define SO_BD2  4096    // float[128]
#define SO_BG1  4608    // float[128]
#define SO_BG2  5120    // float[128]
#define SO_SQ   5632    // float[1024]
#define SO_SCR  9728    // float[8*256]  per-warp 16x16 scratch
#define SO_A    17920   // bf16 128xPA = 34816 B
#define SO_P    52736   // bf16 128xPA = 34816 B
#define SO_W0   87552   // bf16 128xPA
#define SO_W1   122368
#define SO_W2   157184
#define ATTN_SMEM 192000

typedef wmma::fragment<wmma::matrix_a, 16, 16, 16, __nv_bfloat16, wmma::row_major> FragA;
typedef wmma::fragment<wmma::matrix_b, 16, 16, 16, __nv_bfloat16, wmma::row_major> FragB;
typedef wmma::fragment<wmma::accumulator, 16, 16, 16, float> FragC;

__device__ __forceinline__ void gemm_warp(const __nv_bfloat16* sA_,
                                          const __nv_bfloat16* sW_,
                                          int wid, FragC acc[8])
{
#pragma unroll
    for (int j = 0; j < 8; ++j) wmma::fill_fragment(acc[j], 0.0f);
#pragma unroll
    for (int k = 0; k < 8; ++k) {
        FragA a;
        wmma::load_matrix_sync(a, sA_ + (wid*16)*PA + k*16, PA);
#pragma unroll
        for (int j = 0; j < 8; ++j) {
            FragB b;
            wmma::load_matrix_sync(b, sW_ + (k*16)*PA + j*16, PA);
            wmma::mma_sync(acc[j], a, b, acc[j]);
        }
    }
}

__global__ __launch_bounds__(256, 1) void attn_kernel(
    const float* __restrict__ xyz,
    const float* __restrict__ Wd1, const float* __restrict__ bd1,
    const float* __restrict__ bd2, const float* __restrict__ bg1,
    const float* __restrict__ bg2,
    float* __restrict__ out_attn, int write_attn)
{
    extern __shared__ char smem[];
    int*   sI   = (int*)(smem + SO_SI);
    float* sD   = (float*)(smem + SO_SD);
    float* sWd1 = (float*)(smem + SO_WD1);
    float* sBd1 = (float*)(smem + SO_BD1);
    float* sBd2 = (float*)(smem + SO_BD2);
    float* sBg1 = (float*)(smem + SO_BG1);
    float* sBg2 = (float*)(smem + SO_BG2);
    float* sQ   = (float*)(smem + SO_SQ);
    __nv_bfloat16* sA = (__nv_bfloat16*)(smem + SO_A);
    __nv_bfloat16* sP = (__nv_bfloat16*)(smem + SO_P);
    const __nv_bfloat16* sW0 = (const __nv_bfloat16*)(smem + SO_W0);
    const __nv_bfloat16* sW1 = (const __nv_bfloat16*)(smem + SO_W1);
    const __nv_bfloat16* sW2 = (const __nv_bfloat16*)(smem + SO_W2);

    int tid = threadIdx.x, wid = tid >> 5, lane = tid & 31;
    int q0 = blockIdx.x * 8;
    int nbase = q0 & ~(NN - 1);
    float* scr = (float*)(smem + SO_SCR) + wid * 256;

    // ---- init: indices, deltas, q rows, small weights, W tiles (pitch PA) ----
    if (tid < 128) {
        int r = tid;
        int qg = q0 + (r >> 4);
        int idx = g_knn[qg * KNB + (r & 15)];
        sI[r] = idx;
        int cg = nbase + idx;
        sD[r*3+0] = xyz[qg*3+0] - xyz[cg*3+0];
        sD[r*3+1] = xyz[qg*3+1] - xyz[cg*3+1];
        sD[r*3+2] = xyz[qg*3+2] - xyz[cg*3+2];
        sBd1[tid] = bd1[tid]; sBd2[tid] = bd2[tid];
        sBg1[tid] = bg1[tid]; sBg2[tid] = bg2[tid];
    }
    for (int i = tid; i < 1024; i += 256) sQ[i] = g_q[(size_t)q0 * DM + i];
    for (int i = tid; i < 384; i += 256) sWd1[i] = Wd1[i];
    // copy three W tiles (bf16 row-major 128x128 -> pitch PA)
    for (int i = tid; i < 2048; i += 256) {
        int row = i >> 4, ch = i & 15;   // 16B chunks per 256B row
        const uint4* s0 = (const uint4*)(&g_WB[0][row * 128 + ch * 8]);
        const uint4* s1 = (const uint4*)(&g_WB[1][row * 128 + ch * 8]);
        const uint4* s2 = (const uint4*)(&g_WB[2][row * 128 + ch * 8]);
        *(uint4*)((char*)sW0 + row * (PA*2) + ch * 16) = *s0;
        *(uint4*)((char*)sW1 + row * (PA*2) + ch * 16) = *s1;
        *(uint4*)((char*)sW2 + row * (PA*2) + ch * 16) = *s2;
    }
    __syncthreads();

    // ---- T1 = relu(delta @ Wd1 + bd1) -> sA (bf16) ----
    for (int i = 0; i < 8; ++i) {
        int e = i * 256 + tid;
        int r = e >> 4, k0 = (e & 15) << 3;
        float dx = sD[r*3+0], dy = sD[r*3+1], dz = sD[r*3+2];
        uint32_t pk[4];
#pragma unroll
        for (int t = 0; t < 4; ++t) {
            int k = k0 + 2*t;
            float f0 = fmaxf(dx*sWd1[k]   + dy*sWd1[128+k]   + dz*sWd1[256+k]   + sBd1[k],   0.f);
            float f1 = fmaxf(dx*sWd1[k+1] + dy*sWd1[128+k+1] + dz*sWd1[256+k+1] + sBd1[k+1], 0.f);
            pk[t] = pack_bf16(f0, f1);
        }
        *(uint4*)(&sA[r * PA + k0]) = make_uint4(pk[0], pk[1], pk[2], pk[3]);
    }
    __syncthreads();
    // From here on: everything is warp-local (A rows, P rows, scratch, softmax).

    FragC acc[8];
    int r16 = lane >> 1, hf = lane & 1;
    int r   = wid * 16 + r16;             // this thread's output row (row-mode)

    // ================= GEMM1: C = T1 @ Wd2^T ; P = C + bd2 ; H -> sA =================
    gemm_warp(sA, sW0, wid, acc);
    {
        const float* kp = g_k + (size_t)(nbase + sI[r]) * DM;
#pragma unroll
        for (int j = 0; j < 8; ++j) {
            wmma::store_matrix_sync(scr, acc[j], 16, wmma::mem_row_major);
            __syncwarp();
            int cg = j * 16 + hf * 8;
            float C[8], P[8];
#pragma unroll
            for (int t = 0; t < 8; ++t) {
                C[t] = scr[r16 * 16 + hf * 8 + t];
                P[t] = C[t] + sBd2[cg + t];
            }
            *(uint4*)(&sP[r * PA + cg]) = make_uint4(
                pack_bf16(P[0], P[1]), pack_bf16(P[2], P[3]),
                pack_bf16(P[4], P[5]), pack_bf16(P[6], P[7]));
            float4 k0v = *(const float4*)(kp + cg);
            float4 k1v = *(const float4*)(kp + cg + 4);
            const float* qp = &sQ[wid * 128 + cg];
            float H[8];
            H[0] = qp[0] - k0v.x + P[0]; H[1] = qp[1] - k0v.y + P[1];
            H[2] = qp[2] - k0v.z + P[2]; H[3] = qp[3] - k0v.w + P[3];
            H[4] = qp[4] - k1v.x + P[4]; H[5] = qp[5] - k1v.y + P[5];
            H[6] = qp[6] - k1v.z + P[6]; H[7] = qp[7] - k1v.w + P[7];
            *(uint4*)(&sA[r * PA + cg]) = make_uint4(
                pack_bf16(H[0], H[1]), pack_bf16(H[2], H[3]),
                pack_bf16(H[4], H[5]), pack_bf16(H[6], H[7]));
            __syncwarp();
        }
    }

    // ================= GEMM2: C = H @ Wg1^T ; T2 = relu(C + bg1) -> sA =================
    gemm_warp(sA, sW1, wid, acc);
#pragma unroll
    for (int j = 0; j < 8; ++j) {
        wmma::store_matrix_sync(scr, acc[j], 16, wmma::mem_row_major);
        __syncwarp();
        int cg = j * 16 + hf * 8;
        float T[8];
#pragma unroll
        for (int t = 0; t < 8; ++t)
            T[t] = fmaxf(scr[r16 * 16 + hf * 8 + t] + sBg1[cg + t], 0.f);
        *(uint4*)(&sA[r * PA + cg]) = make_uint4(
            pack_bf16(T[0], T[1]), pack_bf16(T[2], T[3]),
            pack_bf16(T[4], T[5]), pack_bf16(T[6], T[7]));
        __syncwarp();
    }

    // ================= GEMM3: logits = T2 @ Wg2^T ; softmax ; outputs =================
    gemm_warp(sA, sW2, wid, acc);
    {
        const float SC = 0.08838834764831845f;   // 1/sqrt(128)
        int c16 = lane & 15, hcol = lane >> 4;   // col-mode ids
        const float* vp = g_v + (size_t)(nbase + sI[r]) * DM;
        size_t arow = ((size_t)(q0 + wid) * KNB + (size_t)r16) * DM;
#pragma unroll
        for (int j = 0; j < 8; ++j) {
            wmma::store_matrix_sync(scr, acc[j], 16, wmma::mem_row_major);
            __syncwarp();
            // col-mode: per-channel softmax over 16 neighbor rows
            float ex[8], s = 0.f;
            float bc = sBg2[j * 16 + c16];
#pragma unroll
            for (int t = 0; t < 8; ++t) {
                float l = scr[(hcol * 8 + t) * 16 + c16];
                ex[t] = expf((l + bc) * SC);
                s += ex[t];
            }
            s += __shfl_xor_sync(0xFFFFFFFFu, s, 16);
            float inv = 1.0f / s;
#pragma unroll
            for (int t = 0; t < 8; ++t)
                scr[(hcol * 8 + t) * 16 + c16] = ex[t] * inv;
            __syncwarp();
            // row-mode: write attn, accumulate res
            int cg = j * 16 + hf * 8;
            float av[8];
#pragma unroll
            for (int t = 0; t < 8; ++t) av[t] = scr[r16 * 16 + hf * 8 + t];
            if (write_attn) {
                *(float4*)(&out_attn[arow + cg])     = make_float4(av[0], av[1], av[2], av[3]);
                *(float4*)(&out_attn[arow + cg + 4]) = make_float4(av[4], av[5], av[6], av[7]);
            }
            float4 v0 = *(const float4*)(vp + cg);
            float4 v1 = *(const float4*)(vp + cg + 4);
            uint4 pb = *(const uint4*)(&sP[r * PA + cg]);
            const __nv_bfloat162* pb2 = (const __nv_bfloat162*)&pb;
            float tacc[8];
            tacc[0] = av[0] * (v0.x + __bfloat162float(pb2[0].x));
            tacc[1] = av[1] * (v0.y + __bfloat162float(pb2[0].y));
            tacc[2] = av[2] * (v0.z + __bfloat162float(pb2[1].x));
            tacc[3] = av[3] * (v0.w + __bfloat162float(pb2[1].y));
            tacc[4] = av[4] * (v1.x + __bfloat162float(pb2[2].x));
            tacc[5] = av[5] * (v1.y + __bfloat162float(pb2[2].y));
            tacc[6] = av[6] * (v1.z + __bfloat162float(pb2[3].x));
            tacc[7] = av[7] * (v1.w + __bfloat162float(pb2[3].y));
#pragma unroll
            for (int t = 0; t < 8; ++t) {
                tacc[t] += __shfl_xor_sync(0xFFFFFFFFu, tacc[t], 2);
                tacc[t] += __shfl_xor_sync(0xFFFFFFFFu, tacc[t], 4);
                tacc[t] += __shfl_xor_sync(0xFFFFFFFFu, tacc[t], 8);
                tacc[t] += __shfl_xor_sync(0xFFFFFFFFu, tacc[t], 16);
            }
            if (r16 == 0) {
                float* rp = &g_res[(size_t)(q0 + wid) * DM + cg];
                *(float4*)rp       = make_float4(tacc[0], tacc[1], tacc[2], tacc[3]);
                *(float4*)(rp + 4) = make_float4(tacc[4], tacc[5], tacc[6], tacc[7]);
            }
            __syncwarp();
        }
    }
}

// =================================================================================
// K4: out_res = g_res @ W2 + b2 + features (unchanged)
// =================================================================================
__global__ __launch_bounds__(256) void final_kernel(
    const float* __restrict__ W2, const float* __restrict__ b2,
    const float* __restrict__ feat, float* __restrict__ out_res)
{
    extern __shared__ float sm[];
    float* sR  = sm;
    float* sW2 = sm + 8192;
    int tid = threadIdx.x;
    int row0 = blockIdx.x * 64;

    for (int i = tid; i < 8192; i += 256) {
        sR[i]  = g_res[(size_t)row0 * DM + i];
        sW2[i] = W2[i];
    }
    __syncthreads();

    int ty = tid >> 5, tx = tid & 31;
    float acc[8][2];
#pragma unroll
    for (int i = 0; i < 8; ++i) { acc[i][0] = 0.f; acc[i][1] = 0.f; }

#pragma unroll 4
    for (int kk = 0; kk < 128; ++kk) {
        float a[8], w[2];
#pragma unroll
        for (int i = 0; i < 8; ++i) a[i] = sR[(ty + 8*i)*128 + kk];
        w[0] = sW2[kk*64 + tx];
        w[1] = sW2[kk*64 + tx + 32];
#pragma unroll
        for (int i = 0; i < 8; ++i) {
            acc[i][0] = fmaf(a[i], w[0], acc[i][0]);
            acc[i][1] = fmaf(a[i], w[1], acc[i][1]);
        }
    }
#pragma unroll
    for (int i = 0; i < 8; ++i)
#pragma unroll
        for (int j = 0; j < 2; ++j) {
            int rr = ty + 8*i, c = tx + 32*j;
            out_res[(size_t)(row0 + rr)*DP + c] =
                acc[i][j] + __ldg(&b2[c]) + feat[(size_t)(row0 + rr)*DP + c];
        }
}

// =================================================================================
// launch
// =================================================================================
extern "C" void kernel_launch(void* const* d_in, const int* in_sizes, int n_in,
                              void* d_out, int out_size)
{
    const float* xyz  = (const float*)d_in[0];
    const float* feat = (const float*)d_in[1];
    const float* W1   = (const float*)d_in[2];
    const float* b1   = (const float*)d_in[3];
    const float* W2   = (const float*)d_in[4];
    const float* b2   = (const float*)d_in[5];
    const float* Wd1  = (const float*)d_in[6];
    const float* bd1  = (const float*)d_in[7];
    const float* Wd2  = (const float*)d_in[8];
    const float* bd2  = (const float*)d_in[9];
    const float* Wg1  = (const float*)d_in[10];
    const float* bg1  = (const float*)d_in[11];
    const float* Wg2  = (const float*)d_in[12];
    const float* bg2  = (const float*)d_in[13];
    const float* Wq   = (const float*)d_in[14];
    const float* Wk   = (const float*)d_in[15];
    const float* Wv   = (const float*)d_in[16];

    float* out = (float*)d_out;
    const long long RES_E = (long long)BN * DP;
    const long long ATT_E = (long long)BN * KNB * DM;

    float* out_res  = out;
    float* out_attn = out;
    int wr = 1, wa = 1;
    long long osz = (long long)out_size;
    if (osz >= RES_E + ATT_E) {
        out_attn = out + RES_E;
    } else if (osz == ATT_E) {
        wr = 0;
    } else {
        wa = 0;
    }

    const size_t PROJ_SMEM = (4096 + 8192 + 16384) * sizeof(float);
    const size_t FIN_SMEM  = 16384 * sizeof(float);

    cudaFuncSetAttribute(proj_kernel,  cudaFuncAttributeMaxDynamicSharedMemorySize, (int)PROJ_SMEM);
    cudaFuncSetAttribute(attn_kernel,  cudaFuncAttributeMaxDynamicSharedMemorySize, ATTN_SMEM);
    cudaFuncSetAttribute(final_kernel, cudaFuncAttributeMaxDynamicSharedMemorySize, (int)FIN_SMEM);

    wprep_kernel<<<3, 256>>>(Wd2, Wg1, Wg2);
    knn_kernel<<<BN / 8, 256>>>(xyz);
    proj_kernel<<<BN / 64, 256, PROJ_SMEM>>>(feat, W1, b1, Wq, Wk, Wv);
    attn_kernel<<<BN / 8, 256, ATTN_SMEM>>>(xyz, Wd1, bd1, bd2, bg1, bg2, out_attn, wa);
    if (wr)
        final_kernel<<<BN / 64, 256, FIN_SMEM>>>(W2, b2, feat, out_res);
}